// round 4
// baseline (speedup 1.0000x reference)
#include <cuda_runtime.h>
#include <cuda_fp16.h>

#define NN 768
#define CC 384
#define CZd 128
#define HHd 16
#define CHD 24
#define NP (NN*NN)
#define INFV 1e9f
#define EPSV 1e-5f

typedef unsigned long long u64;
typedef unsigned int u32;

// ------------------------- device scratch (no runtime alloc) ----------------
__device__ float g_an[NN*CC];
__device__ float g_q[NN*CC];
__device__ float g_k[NN*CC];
__device__ float g_v[NN*CC];
__device__ float g_g[NN*CC];
__device__ float g_o[NN*CC];
__device__ float g_Wpp[2048];          // [c2(64)][h2(8)][hh(2)][par(2)]
__device__ float g_S[HHd];
__device__ float g_Cb[HHd];
__device__ __half g_bias[(size_t)HHd*NP];   // [h][i*768 + j]

// ------------------------- packed f32x2 helpers (sm_103a) -------------------
__device__ __forceinline__ u64 pk2(float x, float y){
    u64 r; asm("mov.b64 %0,{%1,%2};" : "=l"(r) : "r"(__float_as_uint(x)), "r"(__float_as_uint(y))); return r;
}
__device__ __forceinline__ float2 up2(u64 v){
    u32 a,b; asm("mov.b64 {%0,%1},%2;" : "=r"(a), "=r"(b) : "l"(v));
    return make_float2(__uint_as_float(a), __uint_as_float(b));
}
__device__ __forceinline__ u64 ffma2(u64 a, u64 b, u64 c){
    u64 d; asm("fma.rn.f32x2 %0,%1,%2,%3;" : "=l"(d) : "l"(a), "l"(b), "l"(c)); return d;
}
__device__ __forceinline__ u64 fmul2(u64 a, u64 b){
    u64 d; asm("mul.rn.f32x2 %0,%1,%2;" : "=l"(d) : "l"(a), "l"(b)); return d;
}
__device__ __forceinline__ u64 fadd2(u64 a, u64 b){
    u64 d; asm("add.rn.f32x2 %0,%1,%2;" : "=l"(d) : "l"(a), "l"(b)); return d;
}
__device__ __forceinline__ float sigmoidf_(float x){ return 1.f/(1.f + __expf(-x)); }

// ------------------------- kernel 1: fold LN(z) weights ---------------------
__global__ void k_prep(const float* __restrict__ lnzw, const float* __restrict__ lnzb,
                       const float* __restrict__ Wz){
    __shared__ float sw[128][17];
    __shared__ float sb[128][17];
    int c = threadIdx.x;   // 0..127
    float w = lnzw[c], b = lnzb[c];
    #pragma unroll
    for(int h=0; h<16; h++){
        float wz = Wz[c*16 + h];
        float wp = w*wz;
        sw[c][h] = wp;
        sb[c][h] = b*wz;
        // layout: [c2][h2][hh][par] : float4 at (c2*32 + h2*4) = pairs for h=2h2, 2h2+1
        g_Wpp[(c>>1)*32 + (h>>1)*4 + (h&1)*2 + (c&1)] = wp;
    }
    __syncthreads();
    if(c < 16){
        float s = 0.f, cb = 0.f;
        for(int j=0; j<128; j++){ s += sw[j][c]; cb += sb[j][c]; }
        g_S[c] = s; g_Cb[c] = cb;
    }
}

// ------------------------- kernel 2: LayerNorm(a) ---------------------------
__global__ void k_lna(const float* __restrict__ a, const float* __restrict__ w,
                      const float* __restrict__ b){
    int warp = threadIdx.x >> 5, lane = threadIdx.x & 31;
    int row = blockIdx.x*8 + warp;
    const float* ar = a + (size_t)row*CC;
    float v[12]; float s = 0.f, ss = 0.f;
    #pragma unroll
    for(int r=0; r<12; r++){ v[r] = ar[lane + r*32]; s += v[r]; ss += v[r]*v[r]; }
    #pragma unroll
    for(int o=16; o; o>>=1){ s += __shfl_xor_sync(~0u, s, o); ss += __shfl_xor_sync(~0u, ss, o); }
    float mu = s * (1.f/CC);
    float rs = rsqrtf(ss*(1.f/CC) - mu*mu + EPSV);
    float* dr = g_an + (size_t)row*CC;
    #pragma unroll
    for(int r=0; r<12; r++){
        int cc = lane + r*32;
        dr[cc] = (v[r]-mu)*rs*w[cc] + b[cc];
    }
}

// ------------------------- kernel 3: pair bias (fused LN(z)@Wz) -------------
// grid (3, 768): blockIdx.y = i, blockIdx.x = j-tile of 256. 128 threads.
// Thread t owns rows j0+t and j0+t+128, all 16 heads. Each z element read from
// smem exactly once (stats fused into dot pass); w is broadcast LDS.128.
// Staging stores are float2 (stride 34 is 8B- but not 16B-aligned for odd j).
__global__ void __launch_bounds__(128) k_bias(const float* __restrict__ z){
    __shared__ __align__(16) float zs[256*34];    // 34.8KB, stride 34 (conflict-free u64)
    __shared__ __align__(16) float swp[2048];     // 8KB packed Wp
    __shared__ float sS[16], sCb[16];
    int t = threadIdx.x;
    int i  = blockIdx.y;
    int j0 = blockIdx.x*256;
    #pragma unroll
    for(int r=0; r<4; r++)
        *(float4*)&swp[(t + 128*r)*4] = *(const float4*)&g_Wpp[(t + 128*r)*4];
    if(t < 16){ sS[t] = g_S[t]; sCb[t] = g_Cb[t]; }

    const float* zbase = z + ((size_t)i*NN + j0)*CZd;
    float sum0=0.f, ssq0=0.f, sum1=0.f, ssq1=0.f;
    u64 accA[16], accB[16];
    #pragma unroll
    for(int q=0; q<16; q++){ accA[q]=0ull; accB[q]=0ull; }

    #pragma unroll
    for(int p=0; p<4; p++){
        __syncthreads();
        // stage 256 j x 32 c, coalesced float4 gmem loads, float2 smem stores
        #pragma unroll
        for(int r=0; r<16; r++){
            int idx = t + 128*r;
            int j = idx >> 3, c4 = idx & 7;
            float4 zv = *(const float4*)(zbase + (size_t)j*CZd + p*32 + c4*4);
            *(float2*)&zs[j*34 + c4*4]     = make_float2(zv.x, zv.y);
            *(float2*)&zs[j*34 + c4*4 + 2] = make_float2(zv.z, zv.w);
        }
        __syncthreads();
        #pragma unroll
        for(int cl=0; cl<16; cl++){
            u64 z0 = *(const u64*)&zs[t*34 + 2*cl];
            u64 z1 = *(const u64*)&zs[(t+128)*34 + 2*cl];
            float2 a0 = up2(z0), a1 = up2(z1);
            sum0 += a0.x + a0.y; ssq0 = fmaf(a0.x,a0.x,ssq0); ssq0 = fmaf(a0.y,a0.y,ssq0);
            sum1 += a1.x + a1.y; ssq1 = fmaf(a1.x,a1.x,ssq1); ssq1 = fmaf(a1.y,a1.y,ssq1);
            const float4* w4 = (const float4*)&swp[(p*16 + cl)*32];
            #pragma unroll
            for(int h2=0; h2<8; h2++){
                float4 wv = w4[h2];
                u64 wa = pk2(wv.x, wv.y), wb = pk2(wv.z, wv.w);
                accA[2*h2]   = ffma2(z0, wa, accA[2*h2]);
                accA[2*h2+1] = ffma2(z0, wb, accA[2*h2+1]);
                accB[2*h2]   = ffma2(z1, wa, accB[2*h2]);
                accB[2*h2+1] = ffma2(z1, wb, accB[2*h2+1]);
            }
        }
    }
    float muA = sum0*(1.f/128.f), rsA = rsqrtf(ssq0*(1.f/128.f) - muA*muA + EPSV);
    float muB = sum1*(1.f/128.f), rsB = rsqrtf(ssq1*(1.f/128.f) - muB*muB + EPSV);

    __syncthreads();                      // done reading zs; reuse as half staging
    __half* sh = (__half*)zs;             // [h][256 j]
    #pragma unroll
    for(int h=0; h<16; h++){
        float2 dA = up2(accA[h]);
        float2 dB = up2(accB[h]);
        sh[h*256 + t]       = __float2half(rsA*((dA.x+dA.y) - muA*sS[h]) + sCb[h]);
        sh[h*256 + t + 128] = __float2half(rsB*((dB.x+dB.y) - muB*sS[h]) + sCb[h]);
    }
    __syncthreads();
    const u32* shp = (const u32*)sh;
    #pragma unroll
    for(int r=0; r<16; r++){
        int idx = t + 128*r;
        int h = idx >> 7, j2 = idx & 127;
        *(u32*)&g_bias[(size_t)h*NP + (size_t)i*NN + j0 + 2*j2] = shp[h*128 + j2];
    }
}

// ------------------------- kernel 4: QKVG projections -----------------------
__global__ void __launch_bounds__(128) k_proj(const float* __restrict__ Wq,
                                              const float* __restrict__ Wk2,
                                              const float* __restrict__ Wv2,
                                              const float* __restrict__ Wg2,
                                              const float* __restrict__ bg){
    __shared__ __align__(16) float As[64*36];
    __shared__ __align__(16) float Bs[32*68];
    int t = threadIdx.x;
    int n0 = blockIdx.x*64, m0 = blockIdx.y*64, zz = blockIdx.z;
    const float* W = (zz==0) ? Wq : (zz==1) ? Wk2 : (zz==2) ? Wv2 : Wg2;
    float* Cd = (zz==0) ? g_q : (zz==1) ? g_k : (zz==2) ? g_v : g_g;
    u64 acc[4][4];
    #pragma unroll
    for(int r=0;r<4;r++){ acc[r][0]=0; acc[r][1]=0; acc[r][2]=0; acc[r][3]=0; }
    int tm = t & 15, tn = t >> 4;

    for(int k0=0; k0<CC; k0+=32){
        __syncthreads();
        #pragma unroll
        for(int r=0; r<4; r++){
            int idx = t + 128*r;
            int row = idx >> 3, c4 = idx & 7;
            float4 av = *(const float4*)&g_an[(size_t)(m0+row)*CC + k0 + c4*4];
            *(float4*)&As[row*36 + c4*4] = av;
            int kr = idx >> 4, n4 = idx & 15;
            float4 bv = *(const float4*)&W[(size_t)(k0+kr)*CC + n0 + n4*4];
            *(float4*)&Bs[kr*68 + n4*4] = bv;
        }
        __syncthreads();
        #pragma unroll 8
        for(int kk=0; kk<32; kk++){
            u64 b0 = *(const u64*)&Bs[kk*68 + tn*8 + 0];
            u64 b1 = *(const u64*)&Bs[kk*68 + tn*8 + 2];
            u64 b2 = *(const u64*)&Bs[kk*68 + tn*8 + 4];
            u64 b3 = *(const u64*)&Bs[kk*68 + tn*8 + 6];
            #pragma unroll
            for(int r=0; r<4; r++){
                float a = As[(tm + 16*r)*36 + kk];
                u64 a2 = pk2(a, a);
                acc[r][0] = ffma2(a2, b0, acc[r][0]);
                acc[r][1] = ffma2(a2, b1, acc[r][1]);
                acc[r][2] = ffma2(a2, b2, acc[r][2]);
                acc[r][3] = ffma2(a2, b3, acc[r][3]);
            }
        }
    }
    #pragma unroll
    for(int r=0; r<4; r++){
        int m = m0 + tm + 16*r;
        #pragma unroll
        for(int p=0; p<4; p++){
            int n = n0 + tn*8 + 2*p;
            float2 vv = up2(acc[r][p]);
            if(zz == 3){ vv.x += bg[n]; vv.y += bg[n+1]; }
            *(float2*)&Cd[(size_t)m*CC + n] = vv;
        }
    }
}

// ------------------------- kernel 5: attention -------------------------------
// grid (24, 16): blockIdx.x = q-tile of 32, blockIdx.y = h. 256 threads.
// Bias tile staged through smem (fp16 -> fp32 with mask bias folded in).
__global__ void __launch_bounds__(256) k_attn(const float* __restrict__ mask){
    __shared__ __align__(16) float qs[32*26];
    __shared__ __align__(16) float ks[64*26];
    __shared__ __align__(16) float vs[64*26];
    __shared__ float sbf[32*64];
    __shared__ float smb[NN];
    int t = threadIdx.x;
    int h = blockIdx.y, q0 = blockIdx.x*32;
    const float scale = 0.20412414523193154f;  // 24^-0.5

    for(int idx=t; idx<32*24; idx+=256){
        int qq = idx/24, c = idx - qq*24;
        qs[qq*26 + c] = g_q[(size_t)(q0+qq)*CC + h*CHD + c] * scale;
    }
    for(int idx=t; idx<NN; idx+=256) smb[idx] = INFV*(mask[idx] - 1.f);
    __syncthreads();

    int qq = t >> 3, k8 = t & 7;
    u64 qv[12];
    #pragma unroll
    for(int i2=0; i2<12; i2++) qv[i2] = *(const u64*)&qs[qq*26 + 2*i2];

    float mx = -1e30f, l = 0.f;
    u64 acc[12];
    #pragma unroll
    for(int i2=0; i2<12; i2++) acc[i2] = 0ull;
    const size_t hNP = (size_t)h*NP;

    for(int kt=0; kt<NN; kt+=64){
        __syncthreads();
        for(int idx=t; idx<64*24; idx+=256){
            int kk = idx/24, c = idx - kk*24;
            ks[kk*26 + c] = g_k[(size_t)(kt+kk)*CC + h*CHD + c];
            vs[kk*26 + c] = g_v[(size_t)(kt+kk)*CC + h*CHD + c];
        }
        // stage bias tile: 32 q x 64 k halves -> fp32 with mask folded
        #pragma unroll
        for(int r=0; r<4; r++){
            int idx = t + 256*r;          // 0..1023
            int q = idx >> 5, k2 = idx & 31;
            u32 pv = *(const u32*)&g_bias[hNP + (size_t)(q0+q)*NN + kt + 2*k2];
            __half2 hh = *(__half2*)&pv;
            float2 fv = __half22float2(hh);
            sbf[q*64 + 2*k2]     = fv.x + smb[kt + 2*k2];
            sbf[q*64 + 2*k2 + 1] = fv.y + smb[kt + 2*k2 + 1];
        }
        __syncthreads();
        #pragma unroll 4
        for(int ii=0; ii<8; ii++){
            int kk = k8 + ii*8;
            u64 d2 = 0ull;
            #pragma unroll
            for(int i2=0; i2<12; i2++) d2 = ffma2(qv[i2], *(const u64*)&ks[kk*26 + 2*i2], d2);
            float2 dd = up2(d2);
            float s = dd.x + dd.y + sbf[qq*64 + kk];
            if(s > mx){
                float f = __expf(mx - s);
                l *= f;
                u64 f2 = pk2(f, f);
                #pragma unroll
                for(int i2=0; i2<12; i2++) acc[i2] = fmul2(acc[i2], f2);
                mx = s;
            }
            float e = __expf(s - mx);
            l += e;
            u64 e2 = pk2(e, e);
            #pragma unroll
            for(int i2=0; i2<12; i2++) acc[i2] = ffma2(*(const u64*)&vs[kk*26 + 2*i2], e2, acc[i2]);
        }
    }
    // merge the 8 lanes that share a q
    #pragma unroll
    for(int off=1; off<8; off<<=1){
        float om = __shfl_xor_sync(~0u, mx, off);
        float ol = __shfl_xor_sync(~0u, l,  off);
        float nm = fmaxf(mx, om);
        float fs = __expf(mx - nm), fo = __expf(om - nm);
        l = l*fs + ol*fo;
        u64 fs2 = pk2(fs, fs), fo2 = pk2(fo, fo);
        #pragma unroll
        for(int i2=0; i2<12; i2++){
            float2 av = up2(acc[i2]);
            float ox = __shfl_xor_sync(~0u, av.x, off);
            float oy = __shfl_xor_sync(~0u, av.y, off);
            acc[i2] = fadd2(fmul2(acc[i2], fs2), fmul2(pk2(ox, oy), fo2));
        }
        mx = nm;
    }
    if(k8 == 0){
        float inv = 1.f / l;
        u64 iv = pk2(inv, inv);
        float* op = g_o + (size_t)(q0+qq)*CC + h*CHD;
        #pragma unroll
        for(int i2=0; i2<12; i2++){
            float2 vv = up2(fmul2(acc[i2], iv));
            *(float2*)&op[2*i2] = vv;
        }
    }
}

// ------------------------- kernel 6: gated output projection ----------------
__global__ void __launch_bounds__(128) k_oproj(const float* __restrict__ Wo,
                                               const float* __restrict__ bo,
                                               float* __restrict__ out){
    __shared__ __align__(16) float As[64*36];
    __shared__ __align__(16) float Bs[32*68];
    int t = threadIdx.x;
    int n0 = blockIdx.x*64, m0 = blockIdx.y*64;
    u64 acc[4][4];
    #pragma unroll
    for(int r=0;r<4;r++){ acc[r][0]=0; acc[r][1]=0; acc[r][2]=0; acc[r][3]=0; }
    int tm = t & 15, tn = t >> 4;

    for(int k0=0; k0<CC; k0+=32){
        __syncthreads();
        #pragma unroll
        for(int r=0; r<4; r++){
            int idx = t + 128*r;
            int row = idx >> 3, c4 = idx & 7;
            size_t aoff = (size_t)(m0+row)*CC + k0 + c4*4;
            float4 ov = *(const float4*)&g_o[aoff];
            float4 gv = *(const float4*)&g_g[aoff];
            float4 av;
            av.x = ov.x * sigmoidf_(gv.x);
            av.y = ov.y * sigmoidf_(gv.y);
            av.z = ov.z * sigmoidf_(gv.z);
            av.w = ov.w * sigmoidf_(gv.w);
            *(float4*)&As[row*36 + c4*4] = av;
            int kr = idx >> 4, n4 = idx & 15;
            float4 bv = *(const float4*)&Wo[(size_t)(k0+kr)*CC + n0 + n4*4];
            *(float4*)&Bs[kr*68 + n4*4] = bv;
        }
        __syncthreads();
        #pragma unroll 8
        for(int kk=0; kk<32; kk++){
            u64 b0 = *(const u64*)&Bs[kk*68 + tn*8 + 0];
            u64 b1 = *(const u64*)&Bs[kk*68 + tn*8 + 2];
            u64 b2 = *(const u64*)&Bs[kk*68 + tn*8 + 4];
            u64 b3 = *(const u64*)&Bs[kk*68 + tn*8 + 6];
            #pragma unroll
            for(int r=0; r<4; r++){
                float a = As[(tm + 16*r)*36 + kk];
                u64 a2 = pk2(a, a);
                acc[r][0] = ffma2(a2, b0, acc[r][0]);
                acc[r][1] = ffma2(a2, b1, acc[r][1]);
                acc[r][2] = ffma2(a2, b2, acc[r][2]);
                acc[r][3] = ffma2(a2, b3, acc[r][3]);
            }
        }
    }
    #pragma unroll
    for(int r=0; r<4; r++){
        int m = m0 + tm + 16*r;
        #pragma unroll
        for(int p=0; p<4; p++){
            int n = n0 + tn*8 + 2*p;
            float2 vv = up2(acc[r][p]);
            vv.x += bo[n]; vv.y += bo[n+1];
            *(float2*)&out[(size_t)m*CC + n] = vv;
        }
    }
}

// ------------------------- launch -------------------------------------------
extern "C" void kernel_launch(void* const* d_in, const int* in_sizes, int n_in,
                              void* d_out, int out_size){
    const float* a     = (const float*)d_in[0];
    const float* z     = (const float*)d_in[1];
    const float* mask  = (const float*)d_in[2];
    const float* lnaw  = (const float*)d_in[3];
    const float* lnab  = (const float*)d_in[4];
    const float* lnzw  = (const float*)d_in[5];
    const float* lnzb  = (const float*)d_in[6];
    const float* Wz    = (const float*)d_in[7];
    const float* Wq    = (const float*)d_in[8];
    const float* Wk    = (const float*)d_in[9];
    const float* Wv    = (const float*)d_in[10];
    const float* Wg    = (const float*)d_in[11];
    const float* bg    = (const float*)d_in[12];
    const float* Wo    = (const float*)d_in[13];
    const float* bo    = (const float*)d_in[14];
    float* out = (float*)d_out;

    // Fork: side stream runs prep->bias concurrent with lna->proj on the
    // capture (legacy) stream; join via event before attention.
    cudaStream_t s1;
    cudaEvent_t eFork, eJoin;
    cudaStreamCreateWithFlags(&s1, cudaStreamNonBlocking);
    cudaEventCreateWithFlags(&eFork, cudaEventDisableTiming);
    cudaEventCreateWithFlags(&eJoin, cudaEventDisableTiming);

    cudaEventRecord(eFork, 0);
    cudaStreamWaitEvent(s1, eFork, 0);

    k_prep<<<1, 128, 0, s1>>>(lnzw, lnzb, Wz);
    k_bias<<<dim3(3, 768), 128, 0, s1>>>(z);
    cudaEventRecord(eJoin, s1);

    k_lna<<<96, 256>>>(a, lnaw, lnab);
    k_proj<<<dim3(6, 12, 4), 128>>>(Wq, Wk, Wv, Wg, bg);

    cudaStreamWaitEvent(0, eJoin, 0);
    k_attn<<<dim3(24, 16), 256>>>(mask);
    k_oproj<<<dim3(6, 12), 128>>>(Wo, bo, out);
    // note: stream/event objects intentionally not destroyed while capture may
    // be active; kernel_launch is only invoked twice (correctness + capture).
}

// round 5
// speedup vs baseline: 1.1486x; 1.1486x over previous
#include <cuda_runtime.h>
#include <cuda_fp16.h>

#define NN 768
#define CC 384
#define CZd 128
#define HHd 16
#define CHD 24
#define NP (NN*NN)
#define INFV 1e9f
#define EPSV 1e-5f

typedef unsigned long long u64;
typedef unsigned int u32;

// ------------------------- device scratch (no runtime alloc) ----------------
__device__ float g_an[NN*CC];
__device__ float g_q[NN*CC];
__device__ float g_k[NN*CC];
__device__ float g_v[NN*CC];
__device__ float g_g[NN*CC];
__device__ float g_o[NN*CC];
__device__ float g_Wl[2048];           // [c][h] : lnzw[c]*Wz[c][h]
__device__ float g_S[HHd];
__device__ float g_Cb[HHd];
__device__ __half g_bias[(size_t)HHd*NP];   // [h][i*768 + j]

// ------------------------- packed f32x2 helpers (sm_103a) -------------------
__device__ __forceinline__ u64 pk2(float x, float y){
    u64 r; asm("mov.b64 %0,{%1,%2};" : "=l"(r) : "r"(__float_as_uint(x)), "r"(__float_as_uint(y))); return r;
}
__device__ __forceinline__ float2 up2(u64 v){
    u32 a,b; asm("mov.b64 {%0,%1},%2;" : "=r"(a), "=r"(b) : "l"(v));
    return make_float2(__uint_as_float(a), __uint_as_float(b));
}
__device__ __forceinline__ u64 ffma2(u64 a, u64 b, u64 c){
    u64 d; asm("fma.rn.f32x2 %0,%1,%2,%3;" : "=l"(d) : "l"(a), "l"(b), "l"(c)); return d;
}
__device__ __forceinline__ u64 fmul2(u64 a, u64 b){
    u64 d; asm("mul.rn.f32x2 %0,%1,%2;" : "=l"(d) : "l"(a), "l"(b)); return d;
}
__device__ __forceinline__ u64 fadd2(u64 a, u64 b){
    u64 d; asm("add.rn.f32x2 %0,%1,%2;" : "=l"(d) : "l"(a), "l"(b)); return d;
}
__device__ __forceinline__ float sigmoidf_(float x){ return 1.f/(1.f + __expf(-x)); }

// ------------------------- kernel 1: fold LN(z) weights ---------------------
__global__ void k_prep(const float* __restrict__ lnzw, const float* __restrict__ lnzb,
                       const float* __restrict__ Wz){
    __shared__ float sw[128][17];
    __shared__ float sb[128][17];
    int c = threadIdx.x;   // 0..127
    float w = lnzw[c], b = lnzb[c];
    #pragma unroll
    for(int h=0; h<16; h++){
        float wz = Wz[c*16 + h];
        float wp = w*wz;
        sw[c][h] = wp;
        sb[c][h] = b*wz;
        g_Wl[c*16 + h] = wp;          // plain [c][h]
    }
    __syncthreads();
    if(c < 16){
        float s = 0.f, cb = 0.f;
        for(int j=0; j<128; j++){ s += sw[j][c]; cb += sb[j][c]; }
        g_S[c] = s; g_Cb[c] = cb;
    }
}

// ------------------------- kernel 2: LayerNorm(a) ---------------------------
__global__ void k_lna(const float* __restrict__ a, const float* __restrict__ w,
                      const float* __restrict__ b){
    int warp = threadIdx.x >> 5, lane = threadIdx.x & 31;
    int row = blockIdx.x*8 + warp;
    const float* ar = a + (size_t)row*CC;
    float v[12]; float s = 0.f, ss = 0.f;
    #pragma unroll
    for(int r=0; r<12; r++){ v[r] = ar[lane + r*32]; s += v[r]; ss += v[r]*v[r]; }
    #pragma unroll
    for(int o=16; o; o>>=1){ s += __shfl_xor_sync(~0u, s, o); ss += __shfl_xor_sync(~0u, ss, o); }
    float mu = s * (1.f/CC);
    float rs = rsqrtf(ss*(1.f/CC) - mu*mu + EPSV);
    float* dr = g_an + (size_t)row*CC;
    #pragma unroll
    for(int r=0; r<12; r++){
        int cc = lane + r*32;
        dr[cc] = (v[r]-mu)*rs*w[cc] + b[cc];
    }
}

// ------------------------- kernel 3: pair bias (fused LN(z)@Wz) -------------
// grid (3, 768): blockIdx.y = i, blockIdx.x = j-tile of 256. 256 threads.
// Thread t owns row j0+t, all 16 heads (8 u64 h-pair accumulators = 16 regs).
// Stride-36 smem: staging float4 stores and compute LDS.128 conflict-free.
// z touched once from smem; w uniform broadcast LDS.128 from plain [c][h].
__global__ void __launch_bounds__(256) k_bias(const float* __restrict__ z){
    __shared__ __align__(16) float zs[256*36];    // 36KB
    __shared__ __align__(16) float swl[2048];     // 8KB [c][h]
    __shared__ float sS[16], sCb[16];
    int t = threadIdx.x;
    int i  = blockIdx.y;
    int j0 = blockIdx.x*256;
    #pragma unroll
    for(int r=0; r<2; r++)
        *(float4*)&swl[(t + 256*r)*4] = *(const float4*)&g_Wl[(t + 256*r)*4];
    if(t < 16){ sS[t] = g_S[t]; sCb[t] = g_Cb[t]; }

    const float* zbase = z + ((size_t)i*NN + j0)*CZd;
    u64 sum2 = 0ull, ssq2 = 0ull;
    u64 acc[8];
    #pragma unroll
    for(int q=0; q<8; q++) acc[q] = 0ull;

    #pragma unroll
    for(int p=0; p<4; p++){
        __syncthreads();
        // stage 256 j x 32 c; warp = 4 rows x 128B, perfectly coalesced
        #pragma unroll
        for(int r=0; r<8; r++){
            int idx = t + 256*r;
            int j = idx >> 3, c4 = idx & 7;
            *(float4*)&zs[j*36 + c4*4] =
                *(const float4*)(zbase + (size_t)j*CZd + p*32 + c4*4);
        }
        __syncthreads();
        #pragma unroll
        for(int c4=0; c4<8; c4++){
            float4 z4 = *(const float4*)&zs[t*36 + c4*4];
            u64 zlo = pk2(z4.x, z4.y), zhi = pk2(z4.z, z4.w);
            sum2 = fadd2(sum2, zlo); sum2 = fadd2(sum2, zhi);
            ssq2 = ffma2(zlo, zlo, ssq2); ssq2 = ffma2(zhi, zhi, ssq2);
            const float* wb = &swl[(p*32 + c4*4)*16];
            #pragma unroll
            for(int e=0; e<4; e++){
                float ze = (e==0)?z4.x : (e==1)?z4.y : (e==2)?z4.z : z4.w;
                u64 zb = pk2(ze, ze);
                const u64* wp = (const u64*)(wb + e*16);   // 16 floats = 8 h-pairs
                #pragma unroll
                for(int hp=0; hp<8; hp++) acc[hp] = ffma2(zb, wp[hp], acc[hp]);
            }
        }
    }
    float2 sv = up2(sum2), qv = up2(ssq2);
    float mu = (sv.x + sv.y)*(1.f/128.f);
    float rs = rsqrtf((qv.x + qv.y)*(1.f/128.f) - mu*mu + EPSV);

    __syncthreads();                      // done with zs; reuse as half staging
    __half* sh = (__half*)zs;             // [h][256 j]
    #pragma unroll
    for(int hp=0; hp<8; hp++){
        float2 d = up2(acc[hp]);
        sh[(2*hp)*256 + t]   = __float2half(rs*(d.x - mu*sS[2*hp])   + sCb[2*hp]);
        sh[(2*hp+1)*256 + t] = __float2half(rs*(d.y - mu*sS[2*hp+1]) + sCb[2*hp+1]);
    }
    __syncthreads();
    const u32* shp = (const u32*)sh;
    #pragma unroll
    for(int r=0; r<8; r++){
        int idx = t + 256*r;
        int h = idx >> 7, j2 = idx & 127;
        *(u32*)&g_bias[(size_t)h*NP + (size_t)i*NN + j0 + 2*j2] = shp[h*128 + j2];
    }
}

// ------------------------- kernel 4: QKVG projections -----------------------
__global__ void __launch_bounds__(128) k_proj(const float* __restrict__ Wq,
                                              const float* __restrict__ Wk2,
                                              const float* __restrict__ Wv2,
                                              const float* __restrict__ Wg2,
                                              const float* __restrict__ bg){
    __shared__ __align__(16) float As[64*36];
    __shared__ __align__(16) float Bs[32*68];
    int t = threadIdx.x;
    int n0 = blockIdx.x*64, m0 = blockIdx.y*64, zz = blockIdx.z;
    const float* W = (zz==0) ? Wq : (zz==1) ? Wk2 : (zz==2) ? Wv2 : Wg2;
    float* Cd = (zz==0) ? g_q : (zz==1) ? g_k : (zz==2) ? g_v : g_g;
    u64 acc[4][4];
    #pragma unroll
    for(int r=0;r<4;r++){ acc[r][0]=0; acc[r][1]=0; acc[r][2]=0; acc[r][3]=0; }
    int tm = t & 15, tn = t >> 4;

    for(int k0=0; k0<CC; k0+=32){
        __syncthreads();
        #pragma unroll
        for(int r=0; r<4; r++){
            int idx = t + 128*r;
            int row = idx >> 3, c4 = idx & 7;
            float4 av = *(const float4*)&g_an[(size_t)(m0+row)*CC + k0 + c4*4];
            *(float4*)&As[row*36 + c4*4] = av;
            int kr = idx >> 4, n4 = idx & 15;
            float4 bv = *(const float4*)&W[(size_t)(k0+kr)*CC + n0 + n4*4];
            *(float4*)&Bs[kr*68 + n4*4] = bv;
        }
        __syncthreads();
        #pragma unroll 8
        for(int kk=0; kk<32; kk++){
            u64 b0 = *(const u64*)&Bs[kk*68 + tn*8 + 0];
            u64 b1 = *(const u64*)&Bs[kk*68 + tn*8 + 2];
            u64 b2 = *(const u64*)&Bs[kk*68 + tn*8 + 4];
            u64 b3 = *(const u64*)&Bs[kk*68 + tn*8 + 6];
            #pragma unroll
            for(int r=0; r<4; r++){
                float a = As[(tm + 16*r)*36 + kk];
                u64 a2 = pk2(a, a);
                acc[r][0] = ffma2(a2, b0, acc[r][0]);
                acc[r][1] = ffma2(a2, b1, acc[r][1]);
                acc[r][2] = ffma2(a2, b2, acc[r][2]);
                acc[r][3] = ffma2(a2, b3, acc[r][3]);
            }
        }
    }
    #pragma unroll
    for(int r=0; r<4; r++){
        int m = m0 + tm + 16*r;
        #pragma unroll
        for(int p=0; p<4; p++){
            int n = n0 + tn*8 + 2*p;
            float2 vv = up2(acc[r][p]);
            if(zz == 3){ vv.x += bg[n]; vv.y += bg[n+1]; }
            *(float2*)&Cd[(size_t)m*CC + n] = vv;
        }
    }
}

// ------------------------- kernel 5: attention -------------------------------
// grid (24, 16): blockIdx.x = q-tile of 32, blockIdx.y = h. 256 threads.
// Bias tile staged through smem (fp16 -> fp32 with mask bias folded in).
__global__ void __launch_bounds__(256) k_attn(const float* __restrict__ mask){
    __shared__ __align__(16) float qs[32*26];
    __shared__ __align__(16) float ks[64*26];
    __shared__ __align__(16) float vs[64*26];
    __shared__ float sbf[32*64];
    __shared__ float smb[NN];
    int t = threadIdx.x;
    int h = blockIdx.y, q0 = blockIdx.x*32;
    const float scale = 0.20412414523193154f;  // 24^-0.5

    for(int idx=t; idx<32*24; idx+=256){
        int qq = idx/24, c = idx - qq*24;
        qs[qq*26 + c] = g_q[(size_t)(q0+qq)*CC + h*CHD + c] * scale;
    }
    for(int idx=t; idx<NN; idx+=256) smb[idx] = INFV*(mask[idx] - 1.f);
    __syncthreads();

    int qq = t >> 3, k8 = t & 7;
    u64 qv[12];
    #pragma unroll
    for(int i2=0; i2<12; i2++) qv[i2] = *(const u64*)&qs[qq*26 + 2*i2];

    float mx = -1e30f, l = 0.f;
    u64 acc[12];
    #pragma unroll
    for(int i2=0; i2<12; i2++) acc[i2] = 0ull;
    const size_t hNP = (size_t)h*NP;

    for(int kt=0; kt<NN; kt+=64){
        __syncthreads();
        for(int idx=t; idx<64*24; idx+=256){
            int kk = idx/24, c = idx - kk*24;
            ks[kk*26 + c] = g_k[(size_t)(kt+kk)*CC + h*CHD + c];
            vs[kk*26 + c] = g_v[(size_t)(kt+kk)*CC + h*CHD + c];
        }
        // stage bias tile: 32 q x 64 k halves -> fp32 with mask folded
        #pragma unroll
        for(int r=0; r<4; r++){
            int idx = t + 256*r;          // 0..1023
            int q = idx >> 5, k2 = idx & 31;
            u32 pv = *(const u32*)&g_bias[hNP + (size_t)(q0+q)*NN + kt + 2*k2];
            __half2 hh = *(__half2*)&pv;
            float2 fv = __half22float2(hh);
            sbf[q*64 + 2*k2]     = fv.x + smb[kt + 2*k2];
            sbf[q*64 + 2*k2 + 1] = fv.y + smb[kt + 2*k2 + 1];
        }
        __syncthreads();
        #pragma unroll 4
        for(int ii=0; ii<8; ii++){
            int kk = k8 + ii*8;
            u64 d2 = 0ull;
            #pragma unroll
            for(int i2=0; i2<12; i2++) d2 = ffma2(qv[i2], *(const u64*)&ks[kk*26 + 2*i2], d2);
            float2 dd = up2(d2);
            float s = dd.x + dd.y + sbf[qq*64 + kk];
            if(s > mx){
                float f = __expf(mx - s);
                l *= f;
                u64 f2 = pk2(f, f);
                #pragma unroll
                for(int i2=0; i2<12; i2++) acc[i2] = fmul2(acc[i2], f2);
                mx = s;
            }
            float e = __expf(s - mx);
            l += e;
            u64 e2 = pk2(e, e);
            #pragma unroll
            for(int i2=0; i2<12; i2++) acc[i2] = ffma2(*(const u64*)&vs[kk*26 + 2*i2], e2, acc[i2]);
        }
    }
    // merge the 8 lanes that share a q
    #pragma unroll
    for(int off=1; off<8; off<<=1){
        float om = __shfl_xor_sync(~0u, mx, off);
        float ol = __shfl_xor_sync(~0u, l,  off);
        float nm = fmaxf(mx, om);
        float fs = __expf(mx - nm), fo = __expf(om - nm);
        l = l*fs + ol*fo;
        u64 fs2 = pk2(fs, fs), fo2 = pk2(fo, fo);
        #pragma unroll
        for(int i2=0; i2<12; i2++){
            float2 av = up2(acc[i2]);
            float ox = __shfl_xor_sync(~0u, av.x, off);
            float oy = __shfl_xor_sync(~0u, av.y, off);
            acc[i2] = fadd2(fmul2(acc[i2], fs2), fmul2(pk2(ox, oy), fo2));
        }
        mx = nm;
    }
    if(k8 == 0){
        float inv = 1.f / l;
        u64 iv = pk2(inv, inv);
        float* op = g_o + (size_t)(q0+qq)*CC + h*CHD;
        #pragma unroll
        for(int i2=0; i2<12; i2++){
            float2 vv = up2(fmul2(acc[i2], iv));
            *(float2*)&op[2*i2] = vv;
        }
    }
}

// ------------------------- kernel 6: gated output projection ----------------
__global__ void __launch_bounds__(128) k_oproj(const float* __restrict__ Wo,
                                               const float* __restrict__ bo,
                                               float* __restrict__ out){
    __shared__ __align__(16) float As[64*36];
    __shared__ __align__(16) float Bs[32*68];
    int t = threadIdx.x;
    int n0 = blockIdx.x*64, m0 = blockIdx.y*64;
    u64 acc[4][4];
    #pragma unroll
    for(int r=0;r<4;r++){ acc[r][0]=0; acc[r][1]=0; acc[r][2]=0; acc[r][3]=0; }
    int tm = t & 15, tn = t >> 4;

    for(int k0=0; k0<CC; k0+=32){
        __syncthreads();
        #pragma unroll
        for(int r=0; r<4; r++){
            int idx = t + 128*r;
            int row = idx >> 3, c4 = idx & 7;
            size_t aoff = (size_t)(m0+row)*CC + k0 + c4*4;
            float4 ov = *(const float4*)&g_o[aoff];
            float4 gv = *(const float4*)&g_g[aoff];
            float4 av;
            av.x = ov.x * sigmoidf_(gv.x);
            av.y = ov.y * sigmoidf_(gv.y);
            av.z = ov.z * sigmoidf_(gv.z);
            av.w = ov.w * sigmoidf_(gv.w);
            *(float4*)&As[row*36 + c4*4] = av;
            int kr = idx >> 4, n4 = idx & 15;
            float4 bv = *(const float4*)&Wo[(size_t)(k0+kr)*CC + n0 + n4*4];
            *(float4*)&Bs[kr*68 + n4*4] = bv;
        }
        __syncthreads();
        #pragma unroll 8
        for(int kk=0; kk<32; kk++){
            u64 b0 = *(const u64*)&Bs[kk*68 + tn*8 + 0];
            u64 b1 = *(const u64*)&Bs[kk*68 + tn*8 + 2];
            u64 b2 = *(const u64*)&Bs[kk*68 + tn*8 + 4];
            u64 b3 = *(const u64*)&Bs[kk*68 + tn*8 + 6];
            #pragma unroll
            for(int r=0; r<4; r++){
                float a = As[(tm + 16*r)*36 + kk];
                u64 a2 = pk2(a, a);
                acc[r][0] = ffma2(a2, b0, acc[r][0]);
                acc[r][1] = ffma2(a2, b1, acc[r][1]);
                acc[r][2] = ffma2(a2, b2, acc[r][2]);
                acc[r][3] = ffma2(a2, b3, acc[r][3]);
            }
        }
    }
    #pragma unroll
    for(int r=0; r<4; r++){
        int m = m0 + tm + 16*r;
        #pragma unroll
        for(int p=0; p<4; p++){
            int n = n0 + tn*8 + 2*p;
            float2 vv = up2(acc[r][p]);
            vv.x += bo[n]; vv.y += bo[n+1];
            *(float2*)&out[(size_t)m*CC + n] = vv;
        }
    }
}

// ------------------------- launch -------------------------------------------
extern "C" void kernel_launch(void* const* d_in, const int* in_sizes, int n_in,
                              void* d_out, int out_size){
    const float* a     = (const float*)d_in[0];
    const float* z     = (const float*)d_in[1];
    const float* mask  = (const float*)d_in[2];
    const float* lnaw  = (const float*)d_in[3];
    const float* lnab  = (const float*)d_in[4];
    const float* lnzw  = (const float*)d_in[5];
    const float* lnzb  = (const float*)d_in[6];
    const float* Wz    = (const float*)d_in[7];
    const float* Wq    = (const float*)d_in[8];
    const float* Wk    = (const float*)d_in[9];
    const float* Wv    = (const float*)d_in[10];
    const float* Wg    = (const float*)d_in[11];
    const float* bg    = (const float*)d_in[12];
    const float* Wo    = (const float*)d_in[13];
    const float* bo    = (const float*)d_in[14];
    float* out = (float*)d_out;

    // Fork: side stream runs prep->bias concurrent with lna->proj on the
    // capture (legacy) stream; join via event before attention.
    cudaStream_t s1;
    cudaEvent_t eFork, eJoin;
    cudaStreamCreateWithFlags(&s1, cudaStreamNonBlocking);
    cudaEventCreateWithFlags(&eFork, cudaEventDisableTiming);
    cudaEventCreateWithFlags(&eJoin, cudaEventDisableTiming);

    cudaEventRecord(eFork, 0);
    cudaStreamWaitEvent(s1, eFork, 0);

    k_prep<<<1, 128, 0, s1>>>(lnzw, lnzb, Wz);
    k_bias<<<dim3(3, 768), 256, 0, s1>>>(z);
    cudaEventRecord(eJoin, s1);

    k_lna<<<96, 256>>>(a, lnaw, lnab);
    k_proj<<<dim3(6, 12, 4), 128>>>(Wq, Wk, Wv, Wg, bg);

    cudaStreamWaitEvent(0, eJoin, 0);
    k_attn<<<dim3(24, 16), 256>>>(mask);
    k_oproj<<<dim3(6, 12), 128>>>(Wo, bo, out);
    // note: stream/event objects intentionally not destroyed while capture may
    // be active; kernel_launch is only invoked twice (correctness + capture).
}